// round 17
// baseline (speedup 1.0000x reference)
#include <cuda_runtime.h>

// B3-spline UWT (a trous), J=3. x:(16,1024,1024)f32 -> (16,4,1024,1024)f32.
// Kernel A fuses levels 1+2 (vertical-first register chains + H via shuffles,
// c1 staged in smem). Kernel B = level-3 engine with 8-row chains (TY=64):
// 12 streamed rows per warp -> 1.5 loads/output-row, MLP=12.

#define HH 1024
#define WW 1024
#define BB 16
#define HW (HH * WW)

__device__ float g_c2[BB * HW];

__device__ __forceinline__ int refl(int i, int L) {
    if (i < 0) i = -i;
    if (i >= L) i = 2 * L - 2 - i;
    return i;
}

__device__ __forceinline__ float4 shfl_up4(float4 v, int d) {
    float4 r;
    r.x = __shfl_up_sync(0xFFFFFFFFu, v.x, d);
    r.y = __shfl_up_sync(0xFFFFFFFFu, v.y, d);
    r.z = __shfl_up_sync(0xFFFFFFFFu, v.z, d);
    r.w = __shfl_up_sync(0xFFFFFFFFu, v.w, d);
    return r;
}
__device__ __forceinline__ float4 shfl_dn4(float4 v, int d) {
    float4 r;
    r.x = __shfl_down_sync(0xFFFFFFFFu, v.x, d);
    r.y = __shfl_down_sync(0xFFFFFFFFu, v.y, d);
    r.z = __shfl_down_sync(0xFFFFFFFFu, v.z, d);
    r.w = __shfl_down_sync(0xFFFFFFFFu, v.w, d);
    return r;
}

__device__ __forceinline__ float4 ldslow4(const float* row, int g0) {
    float4 v;
    v.x = row[refl(g0 + 0, WW)];
    v.y = row[refl(g0 + 1, WW)];
    v.z = row[refl(g0 + 2, WW)];
    v.w = row[refl(g0 + 3, WW)];
    return v;
}

__device__ __forceinline__ float4 f4axpy(float4 a, float w, float4 v) {
    a.x += w * v.x; a.y += w * v.y; a.z += w * v.z; a.w += w * v.w;
    return a;
}

#define KW0 0.0625f
#define KW1 0.25f
#define KW2 0.375f

// ======================= Kernel A: levels 1+2 fused =======================
__global__ __launch_bounds__(256, 6) void uwt_l12(
    const float* __restrict__ in,     // (B,H,W)
    float* __restrict__ out,          // w1 +0, w2 +HW (bstride 4*HW)
    float* __restrict__ c2p)          // bstride HW
{
    constexpr int TXO = 112;

    __shared__ float s_c1[40][120];

    const int b    = blockIdx.z;
    const int ty0  = blockIdx.y * 32;
    const int tx0  = blockIdx.x * TXO;
    const int tid  = threadIdx.x;
    const int w    = tid >> 5;
    const int lane = tid & 31;

    const float* base = in + b * HW;
    const int  gx    = tx0 - 8 + 4 * lane;
    const bool colIn = (gx >= 0) && (gx + 3 < WW);

    const float W5[5] = { KW0, KW1, KW2, KW1, KW0 };

    float* w1p = out + b * 4 * HW;
    float* w2p = w1p + HW;
    float* c2o = c2p + b * HW;

    // ---- P1: vertical-first chain of 5 c1 rows (cr0..cr0+4) ---------------
    {
        const int cr0 = 5 * w;                // c1 rows, image row ty0-4+cr
        const int yb  = ty0 - 6 + 5 * w;      // first streamed x row

        float4 acc[5];
        #pragma unroll
        for (int t = 0; t < 5; t++) acc[t] = make_float4(0.f, 0.f, 0.f, 0.f);

        if ((yb >= 0) && (yb + 8 < HH) && colIn) {
            const float* p = base + yb * WW + gx;
            #pragma unroll
            for (int j = 0; j < 9; j++, p += WW) {
                float4 v = *(const float4*)p;
                #pragma unroll
                for (int t = 0; t < 5; t++) {
                    const int k = j - t;
                    if (k >= 0 && k <= 4) acc[t] = f4axpy(acc[t], W5[k], v);
                }
            }
        } else {
            #pragma unroll
            for (int j = 0; j < 9; j++) {
                const float* row = base + refl(yb + j, HH) * WW;
                float4 v = colIn ? *(const float4*)(row + gx) : ldslow4(row, gx);
                #pragma unroll
                for (int t = 0; t < 5; t++) {
                    const int k = j - t;
                    if (k >= 0 && k <= 4) acc[t] = f4axpy(acc[t], W5[k], v);
                }
            }
        }

        // H1 via +-1 lane shuffles; lanes 1..30 produce valid c1
        #pragma unroll
        for (int t5 = 0; t5 < 5; t5++) {
            const int cr = cr0 + t5;
            float t[12];
            *(float4*)&t[4] = acc[t5];
            *(float4*)&t[0] = shfl_up4(acc[t5], 1);
            *(float4*)&t[8] = shfl_dn4(acc[t5], 1);

            if (lane >= 1 && lane <= 30) {
                float4 c1;
                c1.x = KW0 * (t[2] + t[6]) + KW1 * (t[3] + t[5]) + KW2 * t[4];
                c1.y = KW0 * (t[3] + t[7]) + KW1 * (t[4] + t[6]) + KW2 * t[5];
                c1.z = KW0 * (t[4] + t[8]) + KW1 * (t[5] + t[7]) + KW2 * t[6];
                c1.w = KW0 * (t[5] + t[9]) + KW1 * (t[6] + t[8]) + KW2 * t[7];
                *(float4*)&s_c1[cr][4 * (lane - 1)] = c1;

                if (cr >= 4 && cr < 36 && lane >= 2 && lane <= 29 && gx < WW) {
                    const int off = (ty0 + cr - 4) * WW + gx;
                    float4 prev = __ldg((const float4*)(base + off));   // L1 hit
                    float4 d = make_float4(prev.x - c1.x, prev.y - c1.y,
                                           prev.z - c1.z, prev.w - c1.w);
                    __stcs((float4*)(w1p + off), d);
                }
            }
        }
    }
    __syncthreads();

    // ---- P2: level 2 (DIL=2) from s_c1; lane m <-> col tx0-4+4m -----------
    {
        const int gxo = tx0 - 4 + 4 * lane;
        const bool doout = (lane >= 1) && (lane <= 28) && (gxo < WW);
        const int r0 = (w >> 1) * 8 + (w & 1);      // c2 rows r0 + 2i

        float4 vwin[5];
        if (lane < 30) {
            #pragma unroll
            for (int k = 0; k < 5; k++)
                vwin[k] = *(const float4*)&s_c1[r0 + 2 * k][4 * lane];
        } else {
            #pragma unroll
            for (int k = 0; k < 5; k++) vwin[k] = make_float4(0.f, 0.f, 0.f, 0.f);
        }

        #pragma unroll
        for (int i = 0; i < 4; i++) {
            const int rr = r0 + 2 * i;

            float4 vv;
            vv.x = KW0 * (vwin[0].x + vwin[4].x) + KW1 * (vwin[1].x + vwin[3].x) + KW2 * vwin[2].x;
            vv.y = KW0 * (vwin[0].y + vwin[4].y) + KW1 * (vwin[1].y + vwin[3].y) + KW2 * vwin[2].y;
            vv.z = KW0 * (vwin[0].z + vwin[4].z) + KW1 * (vwin[1].z + vwin[3].z) + KW2 * vwin[2].z;
            vv.w = KW0 * (vwin[0].w + vwin[4].w) + KW1 * (vwin[1].w + vwin[3].w) + KW2 * vwin[2].w;

            float t[12];
            *(float4*)&t[4] = vv;
            *(float4*)&t[0] = shfl_up4(vv, 1);
            *(float4*)&t[8] = shfl_dn4(vv, 1);

            if (doout) {
                float4 c2;                          // H2: taps +-2, +-4 floats
                c2.x = KW0 * (t[0] + t[8])  + KW1 * (t[2] + t[6])  + KW2 * t[4];
                c2.y = KW0 * (t[1] + t[9])  + KW1 * (t[3] + t[7])  + KW2 * t[5];
                c2.z = KW0 * (t[2] + t[10]) + KW1 * (t[4] + t[8])  + KW2 * t[6];
                c2.w = KW0 * (t[3] + t[11]) + KW1 * (t[5] + t[9])  + KW2 * t[7];

                const float4 c1c = vwin[2];         // c1 at (rr, this col)
                float4 d = make_float4(c1c.x - c2.x, c1c.y - c2.y,
                                       c1c.z - c2.z, c1c.w - c2.w);
                const int off = (ty0 + rr) * WW + gxo;
                __stcs((float4*)(w2p + off), d);
                *(float4*)(c2o + off) = c2;         // keep c2 cacheable for B
            }
            if (i < 3) {
                vwin[0] = vwin[1]; vwin[1] = vwin[2]; vwin[2] = vwin[3]; vwin[3] = vwin[4];
                if (lane < 30)
                    vwin[4] = *(const float4*)&s_c1[r0 + 2 * i + 10][4 * lane];
            }
        }
    }
}

// ======================= Kernel B: level 3, 8-row chains =======================
__global__ __launch_bounds__(256, 4) void uwt_l3(
    const float* __restrict__ in,     // c2, bstride HW
    float* __restrict__ detail,       // w3 plane base (bstride 4*HW)
    float* __restrict__ smooth)       // c3 plane base (bstride 4*HW)
{
    constexpr int DIL = 4, NB = 2, CB = 8;
    constexpr int TXO = 112;

    const int b    = blockIdx.z;
    const int ty0  = blockIdx.y * 64;
    const int tid  = threadIdx.x;
    const int w    = tid >> 5;
    const int lane = tid & 31;

    const int gxv = blockIdx.x * TXO + 4 * (lane - NB);

    const float* base = in + b * HW;
    const float W5[5] = { KW0, KW1, KW2, KW1, KW0 };

    // chain of 8 rows: rr = r0 + 4i, i=0..7; 8 warps cover rows [0,64)
    const int r0 = (w >> 2) * 32 + (w & 3);
    const bool colIn = (gxv >= 0) && (gxv + 3 < WW);

    float4 acc[8];
    #pragma unroll
    for (int i = 0; i < 8; i++) acc[i] = make_float4(0.f, 0.f, 0.f, 0.f);

    auto accum = [&](float4 vj, int j) {
        #pragma unroll
        for (int i = 0; i < 8; i++) {
            const int k = j - i;
            if (k >= 0 && k <= 4) acc[i] = f4axpy(acc[i], W5[k], vj);
        }
    };

    // streamed rows: ty0 + r0 + (j-2)*DIL, j = 0..11
    if ((ty0 + r0 - 2 * DIL >= 0) && (ty0 + r0 + 9 * DIL < HH) && colIn) {
        const float* p = base + (ty0 + r0 - 2 * DIL) * WW + gxv;
        #pragma unroll
        for (int j = 0; j < 12; j++, p += DIL * WW)
            accum(*(const float4*)p, j);
    } else {
        #pragma unroll
        for (int j = 0; j < 12; j++) {
            const int gy = refl(ty0 + r0 + (j - 2) * DIL, HH);
            const float* row = base + gy * WW;
            float4 vj = colIn ? *(const float4*)(row + gxv) : ldslow4(row, gxv);
            accum(vj, j);
        }
    }

    const bool doout = (lane >= NB) && (lane < 32 - NB) && (gxv < WW);

    #pragma unroll
    for (int i = 0; i < 8; i++) {
        float t[4 * (2 * NB + 1)];
        *(float4*)&t[CB] = acc[i];
        #pragma unroll
        for (int d = 1; d <= NB; d++) {
            *(float4*)&t[4 * (NB - d)] = shfl_up4(acc[i], d);
            *(float4*)&t[4 * (NB + d)] = shfl_dn4(acc[i], d);
        }

        if (doout) {
            float4 sm;
            sm.x = KW0 * (t[CB + 0 - 2*DIL] + t[CB + 0 + 2*DIL])
                 + KW1 * (t[CB + 0 -   DIL] + t[CB + 0 +   DIL]) + KW2 * t[CB + 0];
            sm.y = KW0 * (t[CB + 1 - 2*DIL] + t[CB + 1 + 2*DIL])
                 + KW1 * (t[CB + 1 -   DIL] + t[CB + 1 +   DIL]) + KW2 * t[CB + 1];
            sm.z = KW0 * (t[CB + 2 - 2*DIL] + t[CB + 2 + 2*DIL])
                 + KW1 * (t[CB + 2 -   DIL] + t[CB + 2 +   DIL]) + KW2 * t[CB + 2];
            sm.w = KW0 * (t[CB + 3 - 2*DIL] + t[CB + 3 + 2*DIL])
                 + KW1 * (t[CB + 3 -   DIL] + t[CB + 3 +   DIL]) + KW2 * t[CB + 3];

            const int off = (ty0 + r0 + 4 * i) * WW + gxv;
            float4 prev = __ldg((const float4*)(base + off));   // L1 hit (stream)
            float4 dt = make_float4(prev.x - sm.x, prev.y - sm.y,
                                    prev.z - sm.z, prev.w - sm.w);

            __stcs((float4*)(detail + b * 4 * HW + off), dt);
            __stcs((float4*)(smooth + b * 4 * HW + off), sm);
        }
    }
}

extern "C" void kernel_launch(void* const* d_in, const int* in_sizes, int n_in,
                              void* d_out, int out_size)
{
    (void)in_sizes; (void)n_in; (void)out_size;
    const float* x = (const float*)d_in[0];
    float* out = (float*)d_out;

    float* c2;
    cudaGetSymbolAddress((void**)&c2, g_c2);

    dim3 block(256);
    dim3 gridA((WW + 111) / 112, HH / 32, BB);   // 10 x-tiles, 32-row tiles
    dim3 gridB((WW + 111) / 112, HH / 64, BB);   // 10 x-tiles, 64-row tiles

    uwt_l12<<<gridA, block>>>(x, out, c2);
    uwt_l3<<<gridB, block>>>(c2, out + 2 * HW, out + 3 * HW);
}